// round 13
// baseline (speedup 1.0000x reference)
#include <cuda_runtime.h>

#define CC 128
#define AA 64
#define KN 24
#define SS 4
#define NP 276        // 24*23/2
#define NPAIR 10
#define AEVDIM 384
#define RAD 64
#define NATOM (CC*AA)
#define NSL 4         // slices per bucket in angular stage 2

// ---- global scratch (no allocs allowed) ----
__device__ __align__(16) float g_x0[NATOM * AEVDIM];   // sorted AEVs
__device__ __align__(16) float g_e[NATOM];             // per-sorted-row energy
__device__ __align__(16) float g_w1T[SS * 160 * 384];
__device__ __align__(16) float g_w2T[SS * 128 * 160];
__device__ __align__(16) float g_w3T[SS * 96 * 128];
__device__ int g_sortpos[NATOM];
__device__ int g_off[SS], g_cnt[SS];

__constant__ int c_triu[16] = {0,1,2,3, 1,4,5,6, 2,5,7,8, 3,6,8,9};
__constant__ float c_cz[8] = { 0.98078528f, 0.83146961f, 0.55557023f, 0.19509032f,
                              -0.19509032f,-0.55557023f,-0.83146961f,-0.98078528f};
__constant__ float c_sz[8] = { 0.19509032f, 0.55557023f, 0.83146961f, 0.98078528f,
                               0.98078528f, 0.83146961f, 0.55557023f, 0.19509032f};

__device__ __forceinline__ float fsqrt_a(float x) {
    float r; asm("sqrt.approx.f32 %0, %1;" : "=f"(r) : "f"(x)); return r;
}

// ---- f32x2 packed helpers (operands already packed in memory; no movs) ----
__device__ __forceinline__ unsigned long long fma2(
    unsigned long long a, unsigned long long b, unsigned long long c) {
    unsigned long long d;
    asm("fma.rn.f32x2 %0, %1, %2, %3;" : "=l"(d) : "l"(a), "l"(b), "l"(c));
    return d;
}
__device__ __forceinline__ void upk2(unsigned long long v, float& lo, float& hi) {
    asm("mov.b64 {%0, %1}, %2;" : "=f"(lo), "=f"(hi) : "l"(v));
}

// ---------------------------------------------------------------------------
// Kernel 0: prep = species sort (block 0) + weight transpose (blocks 1..296)
// (all work independent; barriers are block-uniform)
// ---------------------------------------------------------------------------
__global__ __launch_bounds__(256) void prep_kernel(
    const int* __restrict__ elem,
    const float* __restrict__ W1, const float* __restrict__ W2, const float* __restrict__ W3)
{
    const int tid = threadIdx.x;
    if (blockIdx.x == 0) {
        __shared__ int tot[SS], off[SS];
        if (tid < SS) tot[tid] = 0;
        __syncthreads();

        int sp[32];
        int lc[SS] = {0,0,0,0};
        const int base = tid * 32;
        #pragma unroll
        for (int i = 0; i < 32; i++) { int s = elem[base + i]; sp[i] = s; lc[s]++; }

        int bas[SS];
        #pragma unroll
        for (int s = 0; s < SS; s++) bas[s] = atomicAdd(&tot[s], lc[s]);
        __syncthreads();

        if (tid == 0) {
            int o = 0;
            for (int s = 0; s < SS; s++) { off[s] = o; g_off[s] = o; g_cnt[s] = tot[s]; o += tot[s]; }
        }
        __syncthreads();

        #pragma unroll
        for (int i = 0; i < 32; i++) {
            int s = sp[i];
            g_sortpos[base + i] = off[s] + bas[s]++;
        }
    } else {
        const int stride = 296 * 256;
        int i0 = (blockIdx.x - 1) * 256 + tid;
        for (int idx = i0; idx < SS * 384 * 160; idx += stride) {
            int s = idx / (384 * 160); int r = idx - s * 384 * 160;
            int f = r / 160, o = r - f * 160;
            g_w1T[(s * 160 + o) * 384 + f] = W1[idx];
        }
        for (int idx = i0; idx < SS * 160 * 128; idx += stride) {
            int s = idx / (160 * 128); int r = idx - s * 160 * 128;
            int f = r / 128, o = r - f * 128;
            g_w2T[(s * 128 + o) * 160 + f] = W2[idx];
        }
        for (int idx = i0; idx < SS * 128 * 96; idx += stride) {
            int s = idx / (128 * 96); int r = idx - s * 128 * 96;
            int f = r / 96, o = r - f * 96;
            g_w3T[(s * 96 + o) * 128 + f] = W3[idx];
        }
    }
}

// ---------------------------------------------------------------------------
// Kernel 1: AEV per atom. One 128-thread block per atom.
// Proven R12 structure; NSL=4 (smaller ascr -> higher residency).
// ---------------------------------------------------------------------------
__global__ __launch_bounds__(128, 12) void aev_kernel(
    const int* __restrict__ elem, const int* __restrict__ nbr,
    const float* __restrict__ dist, const float* __restrict__ diff)
{
    const int id  = blockIdx.x;      // c*64 + a
    const int c   = id >> 6;
    const int tid = threadIdx.x;

    __shared__ __align__(16) float4 nbA[KN];   // ux, uy, uz, a=(d-0.9)/2
    __shared__ __align__(16) float4 nbB[KN];   // R, fca, unused, E2
    __shared__ int   sspec[KN];
    __shared__ float sfca_[KN];
    __shared__ __align__(16) float aev_r[RAD];
    __shared__ int   plist[NP];
    __shared__ __align__(16) float sq[NP], ssn[NP];
    __shared__ __align__(16) float sg0[NP], sg1[NP], sg2[NP], sg3[NP];
    __shared__ int   bcnt[NPAIR], boff[NPAIR + 1], nact;
    __shared__ __align__(16) float ascr[NPAIR][NSL][36];
    __shared__ int   srow;

    if (tid == 0) { srow = g_sortpos[id]; nact = 0; }
    if (tid < NPAIR) bcnt[tid] = 0;
    if (tid < RAD) aev_r[tid] = 0.f;

    if (tid < KN) {
        float d = dist[id * KN + tid];
        const float PI = 3.14159265358979f;
        float fcr = (d < 5.2f) ? (0.5f * __cosf(PI * d / 5.2f) + 0.5f) : 0.f;
        float fca = (d < 3.5f) ? (0.5f * __cosf(PI * d / 3.5f) + 0.5f) : 0.f;
        float inv = 1.0f / d;
        float ux = diff[(id * KN + tid) * 3 + 0] * inv;
        float uy = diff[(id * KN + tid) * 3 + 1] * inv;
        float uz = diff[(id * KN + tid) * 3 + 2] * inv;
        int   sp = elem[c * AA + nbr[id * KN + tid]];
        float a  = 0.5f * d - 0.45f;
        float E2 = __expf(-8.f * a * a);
        float R  = __expf(10.4f * a);
        nbA[tid] = make_float4(ux, uy, uz, a);
        nbB[tid] = make_float4(R, fca, 0.f, E2);
        sspec[tid] = sp;
        sfca_[tid] = fca;

        // radial, windowed +-3 shifts around the nearest one
        float scale = 0.25f * fcr;
        float t     = d - 0.9f;
        int istar = __float2int_rn(t * 3.7209302f);
        istar = max(0, min(15, istar));
        int rlo = max(0, istar - 3), rhi = min(15, istar + 3);
        float ds  = t - 0.26875f * (float)istar;
        float epk = __expf(-16.f * ds * ds);
        const float WW = 0.09913725f;               // exp(-2*1.155625)
        float e = epk;
        float w = __expf(8.6f * t - 1.155625f * (2.f * istar + 1.f));
        for (int r = istar; r <= rhi; r++) {
            atomicAdd(&aev_r[sp * 16 + r], scale * e);
            e *= w; w *= WW;
        }
        e = epk;
        w = __expf(-8.6f * t + 1.155625f * (2.f * istar - 1.f));
        for (int r = istar - 1; r >= rlo; r--) {
            e *= w; w *= WW;
            atomicAdd(&aev_r[sp * 16 + r], scale * e);
        }
    }
    __syncthreads();

    // ---- pass 0: find active pairs (fc12 > 0), count per bucket ----
    for (int p = tid; p < NP; p += 128) {
        int j = 0, rem = p;
        while (rem >= KN - 1 - j) { rem -= KN - 1 - j; j++; }
        int k = j + 1 + rem;

        if (sfca_[j] > 0.f && sfca_[k] > 0.f) {
            int pi = c_triu[sspec[j] * 4 + sspec[k]];
            atomicAdd(&bcnt[pi], 1);
            int pos = atomicAdd(&nact, 1);
            plist[pos] = j | (k << 5) | (pi << 10);
        }
    }
    __syncthreads();

    if (tid == 0) {
        int o = 0;
        #pragma unroll
        for (int u = 0; u < NPAIR; u++) { boff[u] = o; o += bcnt[u]; bcnt[u] = boff[u]; }
        boff[NPAIR] = o;
    }
    __syncthreads();

    // ---- pass 1: per-active-pair math + scatter into buckets ----
    const int na = nact;
    for (int i = tid; i < na; i += 128) {
        int e  = plist[i];
        int j  = e & 31, k = (e >> 5) & 31, pi = e >> 10;
        float4 Aj = nbA[j], Ak = nbA[k];
        float4 Bj = nbB[j], Bk = nbB[k];
        float dot = Aj.x * Ak.x + Aj.y * Ak.y + Aj.z * Ak.z;
        float q   = 0.95f * dot;
        float sn  = fsqrt_a(fmaf(-q, q, 1.f));
        float fc12 = 2.f * Bj.y * Bk.y;
        float X   = __expf(-16.f * Aj.w * Ak.w);
        float f0  = Bj.w * Bk.w * X * fc12;     // fc12 folded into the g's
        float Rp  = Bj.x * Bk.x;
        float f1  = f0 * Rp * 0.0340475f;       // * exp(-3.38)
        float f2  = f1 * Rp * 3.94688e-5f;      // * exp(-10.14)
        float f3  = f2 * Rp * 4.57533e-8f;      // * exp(-16.9)
        int pos = atomicAdd(&bcnt[pi], 1);
        sq[pos]  = q;  ssn[pos] = sn;
        sg0[pos] = f0; sg1[pos] = f1; sg2[pos] = f2; sg3[pos] = f3;
    }
    __syncthreads();

    // ---- stage 2: pair-major, 10 buckets x 4 slices ----
    if (tid < NPAIR * NSL) {
        const int u  = tid / NSL;
        const int sl = tid % NSL;
        float lcz[8], lsz[8];
        #pragma unroll
        for (int z = 0; z < 8; z++) { lcz[z] = c_cz[z]; lsz[z] = c_sz[z]; }

        float acc[32];
        #pragma unroll
        for (int f = 0; f < 32; f++) acc[f] = 0.f;

        const int e0 = boff[u], e1 = boff[u + 1];
        for (int idx = e0 + sl; idx < e1; idx += NSL) {
            float q  = sq[idx], sn = ssn[idx];
            float g0 = sg0[idx], g1 = sg1[idx], g2 = sg2[idx], g3 = sg3[idx];
            #pragma unroll
            for (int z = 0; z < 8; z++) {
                float cd  = fmaf(q, lcz[z], sn * lsz[z]);
                float b   = fmaf(cd, 0.5f, 0.5f);
                float b2 = b*b, b4 = b2*b2, b8 = b4*b4, b16 = b8*b8, b32 = b16*b16;
                acc[z*4+0] = fmaf(b32, g0, acc[z*4+0]);
                acc[z*4+1] = fmaf(b32, g1, acc[z*4+1]);
                acc[z*4+2] = fmaf(b32, g2, acc[z*4+2]);
                acc[z*4+3] = fmaf(b32, g3, acc[z*4+3]);
            }
        }
        #pragma unroll
        for (int f = 0; f < 32; f += 4)
            *reinterpret_cast<float4*>(&ascr[u][sl][f]) =
                make_float4(acc[f], acc[f+1], acc[f+2], acc[f+3]);
    }
    __syncthreads();

    // ---- write AEV row to global (sorted position) ----
    const int row = srow;
    if (tid < RAD) g_x0[row * AEVDIM + tid] = aev_r[tid];
    for (int t = tid; t < NPAIR * 32; t += 128) {
        int u = t >> 5, f = t & 31;
        float s = 0.f;
        #pragma unroll
        for (int sl = 0; sl < NSL; sl++) s += ascr[u][sl][f];
        g_x0[row * AEVDIM + RAD + t] = s;
    }
}

// ---------------------------------------------------------------------------
// Fused MLP: 256 threads, 64 rows/CTA, 8 rows/thread, f32x2 over k-pairs,
// double-buffered weight tiles with register prefetch (1 barrier per tile).
// (exact configuration of the 113.0us best run)
// ---------------------------------------------------------------------------
#define MLP_T  256
#define WBUF_F (160 * 36)     // one w buffer (max FOUT=160)
#define ABUF_F (64 * 36)      // one a buffer
#define H1_F   (64 * 164)
#define H2_F   (64 * 132)
#define DYN_F  (2 * WBUF_F + 2 * ABUF_F + H1_F + H2_F)   // 35072 floats = 140288 B

extern __shared__ float dynsm[];

template<int FIN, int FOUT, int ISTR, int OSTR, bool FROMG>
__device__ __forceinline__ void layerf(
    const float* __restrict__ wT,    // [FOUT][FIN] for this species
    const float* __restrict__ bias,  // [FOUT]
    const float* __restrict__ gin,   // global rows base (FROMG)
    const float* __restrict__ in,    // smem input rows (!FROMG)
    float* __restrict__ out,         // smem output rows
    float* abuf, float* wbuf, int m)
{
    const int tid = threadIdx.x, tx = tid & 31, ty = tid >> 5;  // ty 0..7
    constexpr int NO = FOUT / 32;
    constexpr int NT = FIN / 32;

    unsigned long long acc2[8][NO];   // lanes = (even-k, odd-k) partial sums
    #pragma unroll
    for (int i = 0; i < 8; i++)
        #pragma unroll
        for (int jo = 0; jo < NO; jo++) acc2[i][jo] = 0ull;

    float4 wpre[NO];
    float4 apre[2];

    // prologue: stage tile 0
    #pragma unroll
    for (int j = 0; j < NO; j++) {
        int i = tid + j * MLP_T;
        wpre[j] = *reinterpret_cast<const float4*>(&wT[(i >> 3) * FIN + (i & 7) * 4]);
    }
    if (FROMG) {
        #pragma unroll
        for (int j = 0; j < 2; j++) {
            int i = tid + j * MLP_T;
            int rg = min(i >> 3, m - 1);
            apre[j] = *reinterpret_cast<const float4*>(&gin[rg * FIN + (i & 7) * 4]);
        }
    }
    #pragma unroll
    for (int j = 0; j < NO; j++) {
        int i = tid + j * MLP_T;
        *reinterpret_cast<float4*>(&wbuf[(i >> 3) * 36 + (i & 7) * 4]) = wpre[j];
    }
    if (FROMG) {
        #pragma unroll
        for (int j = 0; j < 2; j++) {
            int i = tid + j * MLP_T;
            *reinterpret_cast<float4*>(&abuf[(i >> 3) * 36 + (i & 7) * 4]) = apre[j];
        }
    }
    __syncthreads();

    for (int t = 0; t < NT; t++) {
        const int cur = t & 1, nxt = cur ^ 1;
        const bool more = (t + 1 < NT);
        const int f1 = (t + 1) * 32;

        if (more) {
            #pragma unroll
            for (int j = 0; j < NO; j++) {
                int i = tid + j * MLP_T;
                wpre[j] = *reinterpret_cast<const float4*>(&wT[(i >> 3) * FIN + f1 + (i & 7) * 4]);
            }
            if (FROMG) {
                #pragma unroll
                for (int j = 0; j < 2; j++) {
                    int i = tid + j * MLP_T;
                    int rg = min(i >> 3, m - 1);
                    apre[j] = *reinterpret_cast<const float4*>(&gin[rg * FIN + f1 + (i & 7) * 4]);
                }
            }
        }

        const float* wb = wbuf + cur * WBUF_F;
        const float* ab = abuf + cur * ABUF_F;
        const int f0 = t * 32;
        #pragma unroll
        for (int g = 0; g < 8; g++) {
            ulonglong2 wv[NO];
            #pragma unroll
            for (int jo = 0; jo < NO; jo++)
                wv[jo] = *reinterpret_cast<const ulonglong2*>(&wb[(tx + 32 * jo) * 36 + 4 * g]);
            #pragma unroll
            for (int i = 0; i < 8; i++) {
                ulonglong2 av;
                if (FROMG)
                    av = *reinterpret_cast<const ulonglong2*>(&ab[(ty * 8 + i) * 36 + 4 * g]);
                else
                    av = *reinterpret_cast<const ulonglong2*>(&in[(ty * 8 + i) * ISTR + f0 + 4 * g]);
                #pragma unroll
                for (int jo = 0; jo < NO; jo++) {
                    acc2[i][jo] = fma2(av.x, wv[jo].x, acc2[i][jo]);
                    acc2[i][jo] = fma2(av.y, wv[jo].y, acc2[i][jo]);
                }
            }
        }

        if (more) {
            float* wn = wbuf + nxt * WBUF_F;
            #pragma unroll
            for (int j = 0; j < NO; j++) {
                int i = tid + j * MLP_T;
                *reinterpret_cast<float4*>(&wn[(i >> 3) * 36 + (i & 7) * 4]) = wpre[j];
            }
            if (FROMG) {
                float* an = abuf + nxt * ABUF_F;
                #pragma unroll
                for (int j = 0; j < 2; j++) {
                    int i = tid + j * MLP_T;
                    *reinterpret_cast<float4*>(&an[(i >> 3) * 36 + (i & 7) * 4]) = apre[j];
                }
            }
        }
        __syncthreads();
    }

    // epilogue: lane-sum + bias + CELU(0.1)
    #pragma unroll
    for (int i = 0; i < 8; i++) {
        int r = ty * 8 + i;
        if (r < m) {
            #pragma unroll
            for (int jo = 0; jo < NO; jo++) {
                int o = tx + 32 * jo;
                float lo, hi; upk2(acc2[i][jo], lo, hi);
                float v = lo + hi + bias[o];
                v = (v > 0.f) ? v : 0.1f * (__expf(v * 10.f) - 1.f);
                out[r * OSTR + o] = v;
            }
        }
    }
}

__global__ __launch_bounds__(MLP_T, 1) void fused_mlp(
    const float* __restrict__ b1, const float* __restrict__ b2,
    const float* __restrict__ b3,
    const float* __restrict__ W4, const float* __restrict__ b4)
{
    const int s  = blockIdx.y;
    const int cnt = g_cnt[s];
    const int rb = blockIdx.x * 64;
    if (rb >= cnt) return;
    const int m   = min(64, cnt - rb);
    const int off = g_off[s];

    float* wbuf = dynsm;                     // 2 x 5760
    float* abuf = dynsm + 2 * WBUF_F;        // 2 x 2304
    float* h1   = abuf + 2 * ABUF_F;         // stride 164 (reused as h3, stride 100)
    float* h2   = h1 + H1_F;                 // stride 132

    const float* gin = g_x0 + (size_t)(off + rb) * AEVDIM;

    layerf<384, 160, 384, 164, true >(g_w1T + s * 160 * 384, b1 + s * 160, gin, h1, h1, abuf, wbuf, m);
    layerf<160, 128, 164, 132, false>(g_w2T + s * 128 * 160, b2 + s * 128, gin, h1, h2, abuf, wbuf, m);
    layerf<128,  96, 132, 100, false>(g_w3T + s *  96 * 128, b3 + s *  96, gin, h2, h1, abuf, wbuf, m);
    __syncthreads();

    // layer 4: 96 -> 1 per row, write per-row energy
    const int tid = threadIdx.x;
    if (tid < m) {
        const float* w4 = W4 + s * 96;
        float a = 0.f;
        #pragma unroll
        for (int f = 0; f < 96; f += 4) {
            float4 hv = *reinterpret_cast<const float4*>(&h1[tid * 100 + f]);
            float4 wv = *reinterpret_cast<const float4*>(&w4[f]);
            a = fmaf(hv.x, wv.x, a);
            a = fmaf(hv.y, wv.y, a);
            a = fmaf(hv.z, wv.z, a);
            a = fmaf(hv.w, wv.w, a);
        }
        g_e[off + rb + tid] = a + b4[s];
    }
}

// ---------------------------------------------------------------------------
// Final: per-molecule sum of atomic energies
// ---------------------------------------------------------------------------
__global__ __launch_bounds__(64) void final_kernel(float* __restrict__ out)
{
    const int c = blockIdx.x, a = threadIdx.x;
    __shared__ float e[AA];
    e[a] = g_e[g_sortpos[c * AA + a]];
    __syncthreads();
    if (a < 32) {
        float v = e[a] + e[a + 32];
        #pragma unroll
        for (int o = 16; o; o >>= 1) v += __shfl_down_sync(0xffffffffu, v, o);
        if (a == 0) out[c] = v;
    }
}

// ---------------------------------------------------------------------------
extern "C" void kernel_launch(void* const* d_in, const int* in_sizes, int n_in,
                              void* d_out, int out_size)
{
    const int*   elem = (const int*)d_in[0];
    const int*   nbr  = (const int*)d_in[1];
    const float* dist = (const float*)d_in[2];
    const float* diff = (const float*)d_in[3];
    const float* W1 = (const float*)d_in[4],  *b1 = (const float*)d_in[5];
    const float* W2 = (const float*)d_in[6],  *b2 = (const float*)d_in[7];
    const float* W3 = (const float*)d_in[8],  *b3 = (const float*)d_in[9];
    const float* W4 = (const float*)d_in[10], *b4 = (const float*)d_in[11];
    float* out = (float*)d_out;

    const int dyn = DYN_F * (int)sizeof(float);   // 140,288 B
    cudaFuncSetAttribute(fused_mlp, cudaFuncAttributeMaxDynamicSharedMemorySize, dyn);

    prep_kernel<<<297, 256>>>(elem, W1, W2, W3);
    aev_kernel<<<NATOM, 128>>>(elem, nbr, dist, diff);
    dim3 g(37, SS);   // 148 CTAs = one full wave; covers species counts to 2368
    fused_mlp<<<g, MLP_T, dyn>>>(b1, b2, b3, W4, b4);
    final_kernel<<<CC, 64>>>(out);
}

// round 14
// speedup vs baseline: 1.0380x; 1.0380x over previous
#include <cuda_runtime.h>

#define CC 128
#define AA 64
#define KN 24
#define SS 4
#define NP 276        // 24*23/2
#define NPAIR 10
#define AEVDIM 384
#define RAD 64
#define NATOM (CC*AA)
#define NSL 8         // slices per bucket in angular stage 2

// ---- global scratch (no allocs allowed) ----
__device__ __align__(16) float g_x0[NATOM * AEVDIM];   // sorted AEVs
__device__ __align__(16) float g_w1T[SS * 160 * 384];
__device__ __align__(16) float g_w2T[SS * 128 * 160];
__device__ __align__(16) float g_w3T[SS * 96 * 128];
__device__ int g_sortpos[NATOM];   // atom -> sorted row
__device__ int g_mol[NATOM];       // sorted row -> molecule id
__device__ int g_off[SS], g_cnt[SS];

__constant__ int c_triu[16] = {0,1,2,3, 1,4,5,6, 2,5,7,8, 3,6,8,9};
__constant__ float c_cz[8] = { 0.98078528f, 0.83146961f, 0.55557023f, 0.19509032f,
                              -0.19509032f,-0.55557023f,-0.83146961f,-0.98078528f};
__constant__ float c_sz[8] = { 0.19509032f, 0.55557023f, 0.83146961f, 0.98078528f,
                               0.98078528f, 0.83146961f, 0.55557023f, 0.19509032f};

__device__ __forceinline__ float fsqrt_a(float x) {
    float r; asm("sqrt.approx.f32 %0, %1;" : "=f"(r) : "f"(x)); return r;
}

// ---- f32x2 packed helpers (operands already packed in memory; no movs) ----
__device__ __forceinline__ unsigned long long fma2(
    unsigned long long a, unsigned long long b, unsigned long long c) {
    unsigned long long d;
    asm("fma.rn.f32x2 %0, %1, %2, %3;" : "=l"(d) : "l"(a), "l"(b), "l"(c));
    return d;
}
__device__ __forceinline__ void upk2(unsigned long long v, float& lo, float& hi) {
    asm("mov.b64 {%0, %1}, %2;" : "=f"(lo), "=f"(hi) : "l"(v));
}

// ---------------------------------------------------------------------------
// Kernel 0: prep = species sort + out zeroing (block 0), wT (blocks 1..296)
// ---------------------------------------------------------------------------
__global__ __launch_bounds__(256) void prep_kernel(
    const int* __restrict__ elem, float* __restrict__ out,
    const float* __restrict__ W1, const float* __restrict__ W2, const float* __restrict__ W3)
{
    const int tid = threadIdx.x;
    if (blockIdx.x == 0) {
        __shared__ int tot[SS], off[SS];
        if (tid < SS) tot[tid] = 0;
        if (tid < CC) out[tid] = 0.f;          // zero output accumulators
        __syncthreads();

        int sp[32];
        int lc[SS] = {0,0,0,0};
        const int base = tid * 32;
        #pragma unroll
        for (int i = 0; i < 32; i++) { int s = elem[base + i]; sp[i] = s; lc[s]++; }

        int bas[SS];
        #pragma unroll
        for (int s = 0; s < SS; s++) bas[s] = atomicAdd(&tot[s], lc[s]);
        __syncthreads();

        if (tid == 0) {
            int o = 0;
            for (int s = 0; s < SS; s++) { off[s] = o; g_off[s] = o; g_cnt[s] = tot[s]; o += tot[s]; }
        }
        __syncthreads();

        #pragma unroll
        for (int i = 0; i < 32; i++) {
            int s = sp[i];
            int pos = off[s] + bas[s]++;
            g_sortpos[base + i] = pos;
            g_mol[pos] = (base + i) >> 6;      // molecule id for this sorted row
        }
    } else {
        const int stride = 296 * 256;
        int i0 = (blockIdx.x - 1) * 256 + tid;
        for (int idx = i0; idx < SS * 384 * 160; idx += stride) {
            int s = idx / (384 * 160); int r = idx - s * 384 * 160;
            int f = r / 160, o = r - f * 160;
            g_w1T[(s * 160 + o) * 384 + f] = W1[idx];
        }
        for (int idx = i0; idx < SS * 160 * 128; idx += stride) {
            int s = idx / (160 * 128); int r = idx - s * 160 * 128;
            int f = r / 128, o = r - f * 128;
            g_w2T[(s * 128 + o) * 160 + f] = W2[idx];
        }
        for (int idx = i0; idx < SS * 128 * 96; idx += stride) {
            int s = idx / (128 * 96); int r = idx - s * 128 * 96;
            int f = r / 96, o = r - f * 96;
            g_w3T[(s * 96 + o) * 128 + f] = W3[idx];
        }
    }
}

// ---------------------------------------------------------------------------
// Kernel 1: AEV per atom. One 128-thread block per atom. (exact R12 structure)
// ---------------------------------------------------------------------------
__global__ __launch_bounds__(128) void aev_kernel(
    const int* __restrict__ elem, const int* __restrict__ nbr,
    const float* __restrict__ dist, const float* __restrict__ diff)
{
    const int id  = blockIdx.x;      // c*64 + a
    const int c   = id >> 6;
    const int tid = threadIdx.x;

    __shared__ __align__(16) float4 nbA[KN];   // ux, uy, uz, a=(d-0.9)/2
    __shared__ __align__(16) float4 nbB[KN];   // R, fca, unused, E2
    __shared__ int   sspec[KN];
    __shared__ float sfca_[KN];
    __shared__ __align__(16) float aev_r[RAD];
    __shared__ int   plist[NP];
    __shared__ __align__(16) float sq[NP], ssn[NP];
    __shared__ __align__(16) float sg0[NP], sg1[NP], sg2[NP], sg3[NP];
    __shared__ int   bcnt[NPAIR], boff[NPAIR + 1], nact;
    __shared__ __align__(16) float ascr[NPAIR][NSL][36];
    __shared__ int   srow;

    if (tid == 0) { srow = g_sortpos[id]; nact = 0; }
    if (tid < NPAIR) bcnt[tid] = 0;
    if (tid < RAD) aev_r[tid] = 0.f;

    if (tid < KN) {
        float d = dist[id * KN + tid];
        const float PI = 3.14159265358979f;
        float fcr = (d < 5.2f) ? (0.5f * __cosf(PI * d / 5.2f) + 0.5f) : 0.f;
        float fca = (d < 3.5f) ? (0.5f * __cosf(PI * d / 3.5f) + 0.5f) : 0.f;
        float inv = 1.0f / d;
        float ux = diff[(id * KN + tid) * 3 + 0] * inv;
        float uy = diff[(id * KN + tid) * 3 + 1] * inv;
        float uz = diff[(id * KN + tid) * 3 + 2] * inv;
        int   sp = elem[c * AA + nbr[id * KN + tid]];
        float a  = 0.5f * d - 0.45f;
        float E2 = __expf(-8.f * a * a);
        float R  = __expf(10.4f * a);
        nbA[tid] = make_float4(ux, uy, uz, a);
        nbB[tid] = make_float4(R, fca, 0.f, E2);
        sspec[tid] = sp;
        sfca_[tid] = fca;

        // radial, windowed +-3 shifts around the nearest one
        float scale = 0.25f * fcr;
        float t     = d - 0.9f;
        int istar = __float2int_rn(t * 3.7209302f);
        istar = max(0, min(15, istar));
        int rlo = max(0, istar - 3), rhi = min(15, istar + 3);
        float ds  = t - 0.26875f * (float)istar;
        float epk = __expf(-16.f * ds * ds);
        const float WW = 0.09913725f;               // exp(-2*1.155625)
        float e = epk;
        float w = __expf(8.6f * t - 1.155625f * (2.f * istar + 1.f));
        for (int r = istar; r <= rhi; r++) {
            atomicAdd(&aev_r[sp * 16 + r], scale * e);
            e *= w; w *= WW;
        }
        e = epk;
        w = __expf(-8.6f * t + 1.155625f * (2.f * istar - 1.f));
        for (int r = istar - 1; r >= rlo; r--) {
            e *= w; w *= WW;
            atomicAdd(&aev_r[sp * 16 + r], scale * e);
        }
    }
    __syncthreads();

    // ---- pass 0: find active pairs (fc12 > 0), count per bucket ----
    for (int p = tid; p < NP; p += 128) {
        int j = 0, rem = p;
        while (rem >= KN - 1 - j) { rem -= KN - 1 - j; j++; }
        int k = j + 1 + rem;

        if (sfca_[j] > 0.f && sfca_[k] > 0.f) {
            int pi = c_triu[sspec[j] * 4 + sspec[k]];
            atomicAdd(&bcnt[pi], 1);
            int pos = atomicAdd(&nact, 1);
            plist[pos] = j | (k << 5) | (pi << 10);
        }
    }
    __syncthreads();

    if (tid == 0) {
        int o = 0;
        #pragma unroll
        for (int u = 0; u < NPAIR; u++) { boff[u] = o; o += bcnt[u]; bcnt[u] = boff[u]; }
        boff[NPAIR] = o;
    }
    __syncthreads();

    // ---- pass 1: per-active-pair math + scatter into buckets ----
    const int na = nact;
    for (int i = tid; i < na; i += 128) {
        int e  = plist[i];
        int j  = e & 31, k = (e >> 5) & 31, pi = e >> 10;
        float4 Aj = nbA[j], Ak = nbA[k];
        float4 Bj = nbB[j], Bk = nbB[k];
        float dot = Aj.x * Ak.x + Aj.y * Ak.y + Aj.z * Ak.z;
        float q   = 0.95f * dot;
        float sn  = fsqrt_a(fmaf(-q, q, 1.f));
        float fc12 = 2.f * Bj.y * Bk.y;
        float X   = __expf(-16.f * Aj.w * Ak.w);
        float f0  = Bj.w * Bk.w * X * fc12;     // fc12 folded into the g's
        float Rp  = Bj.x * Bk.x;
        float f1  = f0 * Rp * 0.0340475f;       // * exp(-3.38)
        float f2  = f1 * Rp * 3.94688e-5f;      // * exp(-10.14)
        float f3  = f2 * Rp * 4.57533e-8f;      // * exp(-16.9)
        int pos = atomicAdd(&bcnt[pi], 1);
        sq[pos]  = q;  ssn[pos] = sn;
        sg0[pos] = f0; sg1[pos] = f1; sg2[pos] = f2; sg3[pos] = f3;
    }
    __syncthreads();

    // ---- stage 2: pair-major, 10 buckets x 8 slices ----
    if (tid < NPAIR * NSL) {
        const int u  = tid >> 3;
        const int sl = tid & 7;
        float lcz[8], lsz[8];
        #pragma unroll
        for (int z = 0; z < 8; z++) { lcz[z] = c_cz[z]; lsz[z] = c_sz[z]; }

        float acc[32];
        #pragma unroll
        for (int f = 0; f < 32; f++) acc[f] = 0.f;

        const int e0 = boff[u], e1 = boff[u + 1];
        for (int idx = e0 + sl; idx < e1; idx += NSL) {
            float q  = sq[idx], sn = ssn[idx];
            float g0 = sg0[idx], g1 = sg1[idx], g2 = sg2[idx], g3 = sg3[idx];
            #pragma unroll
            for (int z = 0; z < 8; z++) {
                float cd  = fmaf(q, lcz[z], sn * lsz[z]);
                float b   = fmaf(cd, 0.5f, 0.5f);
                float b2 = b*b, b4 = b2*b2, b8 = b4*b4, b16 = b8*b8, b32 = b16*b16;
                acc[z*4+0] = fmaf(b32, g0, acc[z*4+0]);
                acc[z*4+1] = fmaf(b32, g1, acc[z*4+1]);
                acc[z*4+2] = fmaf(b32, g2, acc[z*4+2]);
                acc[z*4+3] = fmaf(b32, g3, acc[z*4+3]);
            }
        }
        #pragma unroll
        for (int f = 0; f < 32; f += 4)
            *reinterpret_cast<float4*>(&ascr[u][sl][f]) =
                make_float4(acc[f], acc[f+1], acc[f+2], acc[f+3]);
    }
    __syncthreads();

    // ---- write AEV row to global (sorted position) ----
    const int row = srow;
    if (tid < RAD) g_x0[row * AEVDIM + tid] = aev_r[tid];
    for (int t = tid; t < NPAIR * 32; t += 128) {
        int u = t >> 5, f = t & 31;
        float s = 0.f;
        #pragma unroll
        for (int sl = 0; sl < NSL; sl++) s += ascr[u][sl][f];
        g_x0[row * AEVDIM + RAD + t] = s;
    }
}

// ---------------------------------------------------------------------------
// Fused MLP: 256 threads, 64 rows/CTA, 8 rows/thread, f32x2 over k-pairs,
// double-buffered weight tiles; layer-4 energy accumulated into out[] by REDG.
// ---------------------------------------------------------------------------
#define MLP_T  256
#define WBUF_F (160 * 36)     // one w buffer (max FOUT=160)
#define ABUF_F (64 * 36)      // one a buffer
#define H1_F   (64 * 164)
#define H2_F   (64 * 132)
#define DYN_F  (2 * WBUF_F + 2 * ABUF_F + H1_F + H2_F)   // 35072 floats = 140288 B

extern __shared__ float dynsm[];

template<int FIN, int FOUT, int ISTR, int OSTR, bool FROMG>
__device__ __forceinline__ void layerf(
    const float* __restrict__ wT,    // [FOUT][FIN] for this species
    const float* __restrict__ bias,  // [FOUT]
    const float* __restrict__ gin,   // global rows base (FROMG)
    const float* __restrict__ in,    // smem input rows (!FROMG)
    float* __restrict__ out,         // smem output rows
    float* abuf, float* wbuf, int m)
{
    const int tid = threadIdx.x, tx = tid & 31, ty = tid >> 5;  // ty 0..7
    constexpr int NO = FOUT / 32;
    constexpr int NT = FIN / 32;

    unsigned long long acc2[8][NO];   // lanes = (even-k, odd-k) partial sums
    #pragma unroll
    for (int i = 0; i < 8; i++)
        #pragma unroll
        for (int jo = 0; jo < NO; jo++) acc2[i][jo] = 0ull;

    float4 wpre[NO];
    float4 apre[2];

    // prologue: stage tile 0
    #pragma unroll
    for (int j = 0; j < NO; j++) {
        int i = tid + j * MLP_T;
        wpre[j] = *reinterpret_cast<const float4*>(&wT[(i >> 3) * FIN + (i & 7) * 4]);
    }
    if (FROMG) {
        #pragma unroll
        for (int j = 0; j < 2; j++) {
            int i = tid + j * MLP_T;
            int rg = min(i >> 3, m - 1);
            apre[j] = *reinterpret_cast<const float4*>(&gin[rg * FIN + (i & 7) * 4]);
        }
    }
    #pragma unroll
    for (int j = 0; j < NO; j++) {
        int i = tid + j * MLP_T;
        *reinterpret_cast<float4*>(&wbuf[(i >> 3) * 36 + (i & 7) * 4]) = wpre[j];
    }
    if (FROMG) {
        #pragma unroll
        for (int j = 0; j < 2; j++) {
            int i = tid + j * MLP_T;
            *reinterpret_cast<float4*>(&abuf[(i >> 3) * 36 + (i & 7) * 4]) = apre[j];
        }
    }
    __syncthreads();

    for (int t = 0; t < NT; t++) {
        const int cur = t & 1, nxt = cur ^ 1;
        const bool more = (t + 1 < NT);
        const int f1 = (t + 1) * 32;

        if (more) {
            #pragma unroll
            for (int j = 0; j < NO; j++) {
                int i = tid + j * MLP_T;
                wpre[j] = *reinterpret_cast<const float4*>(&wT[(i >> 3) * FIN + f1 + (i & 7) * 4]);
            }
            if (FROMG) {
                #pragma unroll
                for (int j = 0; j < 2; j++) {
                    int i = tid + j * MLP_T;
                    int rg = min(i >> 3, m - 1);
                    apre[j] = *reinterpret_cast<const float4*>(&gin[rg * FIN + f1 + (i & 7) * 4]);
                }
            }
        }

        const float* wb = wbuf + cur * WBUF_F;
        const float* ab = abuf + cur * ABUF_F;
        const int f0 = t * 32;
        #pragma unroll
        for (int g = 0; g < 8; g++) {
            ulonglong2 wv[NO];
            #pragma unroll
            for (int jo = 0; jo < NO; jo++)
                wv[jo] = *reinterpret_cast<const ulonglong2*>(&wb[(tx + 32 * jo) * 36 + 4 * g]);
            #pragma unroll
            for (int i = 0; i < 8; i++) {
                ulonglong2 av;
                if (FROMG)
                    av = *reinterpret_cast<const ulonglong2*>(&ab[(ty * 8 + i) * 36 + 4 * g]);
                else
                    av = *reinterpret_cast<const ulonglong2*>(&in[(ty * 8 + i) * ISTR + f0 + 4 * g]);
                #pragma unroll
                for (int jo = 0; jo < NO; jo++) {
                    acc2[i][jo] = fma2(av.x, wv[jo].x, acc2[i][jo]);
                    acc2[i][jo] = fma2(av.y, wv[jo].y, acc2[i][jo]);
                }
            }
        }

        if (more) {
            float* wn = wbuf + nxt * WBUF_F;
            #pragma unroll
            for (int j = 0; j < NO; j++) {
                int i = tid + j * MLP_T;
                *reinterpret_cast<float4*>(&wn[(i >> 3) * 36 + (i & 7) * 4]) = wpre[j];
            }
            if (FROMG) {
                float* an = abuf + nxt * ABUF_F;
                #pragma unroll
                for (int j = 0; j < 2; j++) {
                    int i = tid + j * MLP_T;
                    *reinterpret_cast<float4*>(&an[(i >> 3) * 36 + (i & 7) * 4]) = apre[j];
                }
            }
        }
        __syncthreads();
    }

    // epilogue: lane-sum + bias + CELU(0.1)
    #pragma unroll
    for (int i = 0; i < 8; i++) {
        int r = ty * 8 + i;
        if (r < m) {
            #pragma unroll
            for (int jo = 0; jo < NO; jo++) {
                int o = tx + 32 * jo;
                float lo, hi; upk2(acc2[i][jo], lo, hi);
                float v = lo + hi + bias[o];
                v = (v > 0.f) ? v : 0.1f * (__expf(v * 10.f) - 1.f);
                out[r * OSTR + o] = v;
            }
        }
    }
}

__global__ __launch_bounds__(MLP_T, 1) void fused_mlp(
    const float* __restrict__ b1, const float* __restrict__ b2,
    const float* __restrict__ b3,
    const float* __restrict__ W4, const float* __restrict__ b4,
    float* __restrict__ out)
{
    const int s  = blockIdx.y;
    const int cnt = g_cnt[s];
    const int rb = blockIdx.x * 64;
    if (rb >= cnt) return;
    const int m   = min(64, cnt - rb);
    const int off = g_off[s];

    float* wbuf = dynsm;                     // 2 x 5760
    float* abuf = dynsm + 2 * WBUF_F;        // 2 x 2304
    float* h1   = abuf + 2 * ABUF_F;         // stride 164 (reused as h3, stride 100)
    float* h2   = h1 + H1_F;                 // stride 132

    const float* gin = g_x0 + (size_t)(off + rb) * AEVDIM;

    layerf<384, 160, 384, 164, true >(g_w1T + s * 160 * 384, b1 + s * 160, gin, h1, h1, abuf, wbuf, m);
    layerf<160, 128, 164, 132, false>(g_w2T + s * 128 * 160, b2 + s * 128, gin, h1, h2, abuf, wbuf, m);
    layerf<128,  96, 132, 100, false>(g_w3T + s *  96 * 128, b3 + s *  96, gin, h2, h1, abuf, wbuf, m);
    __syncthreads();

    // layer 4: 96 -> 1 per row; accumulate straight into the molecule energy
    const int tid = threadIdx.x;
    if (tid < m) {
        const int row = off + rb + tid;
        const float* w4 = W4 + s * 96;
        float a = 0.f;
        #pragma unroll
        for (int f = 0; f < 96; f += 4) {
            float4 hv = *reinterpret_cast<const float4*>(&h1[tid * 100 + f]);
            float4 wv = *reinterpret_cast<const float4*>(&w4[f]);
            a = fmaf(hv.x, wv.x, a);
            a = fmaf(hv.y, wv.y, a);
            a = fmaf(hv.z, wv.z, a);
            a = fmaf(hv.w, wv.w, a);
        }
        atomicAdd(&out[g_mol[row]], a + b4[s]);   // REDG, 128 distinct addrs
    }
}

// ---------------------------------------------------------------------------
extern "C" void kernel_launch(void* const* d_in, const int* in_sizes, int n_in,
                              void* d_out, int out_size)
{
    const int*   elem = (const int*)d_in[0];
    const int*   nbr  = (const int*)d_in[1];
    const float* dist = (const float*)d_in[2];
    const float* diff = (const float*)d_in[3];
    const float* W1 = (const float*)d_in[4],  *b1 = (const float*)d_in[5];
    const float* W2 = (const float*)d_in[6],  *b2 = (const float*)d_in[7];
    const float* W3 = (const float*)d_in[8],  *b3 = (const float*)d_in[9];
    const float* W4 = (const float*)d_in[10], *b4 = (const float*)d_in[11];
    float* out = (float*)d_out;

    const int dyn = DYN_F * (int)sizeof(float);   // 140,288 B
    cudaFuncSetAttribute(fused_mlp, cudaFuncAttributeMaxDynamicSharedMemorySize, dyn);

    prep_kernel<<<297, 256>>>(elem, out, W1, W2, W3);
    aev_kernel<<<NATOM, 128>>>(elem, nbr, dist, diff);
    dim3 g(37, SS);   // 148 CTAs = one full wave; covers species counts to 2368
    fused_mlp<<<g, MLP_T, dyn>>>(b1, b2, b3, W4, b4, out);
}